// round 1
// baseline (speedup 1.0000x reference)
#include <cuda_runtime.h>
#include <math.h>

#define NCOMP 20

// Warp-per-event Hawkes intensity.
//   out[e] = softplus(<emb_src[src[e]], emb_dst[dst[e]]>)
//          + [exists prev] * alpha * sigmoid((x_last-0.5)/0.25) * exp(-beta*(t[e]-t_last))
// where "prev" = last index i with t_pad[e][i] < t[e]  (rows sorted ascending).
__global__ void markov_kernel(const int* __restrict__ src,
                              const int* __restrict__ dst,
                              const float* __restrict__ t,
                              const float* __restrict__ x_pad,
                              const float* __restrict__ t_pad,
                              const float* __restrict__ emb_src,
                              const float* __restrict__ emb_dst,
                              const float* __restrict__ alpha_p,
                              const float* __restrict__ beta_p,
                              float* __restrict__ out,
                              int E, int L)
{
    const int lane = threadIdx.x & 31;
    const int e = (blockIdx.x * blockDim.x + threadIdx.x) >> 5;
    if (e >= E) return;

    const float tq = __ldg(&t[e]);
    const float* __restrict__ row = t_pad + (size_t)e * L;

    // ---- 32-ary search, round 1: chunk boundaries (L/32 floats per chunk) ----
    const int chunkw = L >> 5;                       // 64 for L=2048
    float vb = __ldg(&row[(lane + 1) * chunkw - 1]); // last element of each chunk
    unsigned b = __ballot_sync(0xffffffffu, vb < tq);
    int chunk = __popc(b);                           // chunks entirely below tq

    int cnt;
    if (chunk >= 32) {
        cnt = L;                                     // all history < tq
    } else {
        // ---- round 2: scan the 64-float chunk, 2 floats/lane, coalesced ----
        const float* cbase = row + chunk * chunkw;
        float2 p = *reinterpret_cast<const float2*>(cbase + lane * 2);
        unsigned b0 = __ballot_sync(0xffffffffu, p.x < tq);
        unsigned b1 = __ballot_sync(0xffffffffu, p.y < tq);
        cnt = chunk * chunkw + __popc(b0) + __popc(b1);
    }

    const bool has_prev = (cnt > 0);
    const int idx = has_prev ? (cnt - 1) : 0;

    // ---- base rate: 20-dim dot across lanes 0..19, xor-shuffle reduce ----
    float prod = 0.0f;
    if (lane < NCOMP) {
        const int s = __ldg(&src[e]);
        const int d = __ldg(&dst[e]);
        prod = __ldg(&emb_src[(size_t)s * NCOMP + lane]) *
               __ldg(&emb_dst[(size_t)d * NCOMP + lane]);
    }
    #pragma unroll
    for (int off = 16; off > 0; off >>= 1)
        prod += __shfl_xor_sync(0xffffffffu, prod, off);
    // all lanes now hold the full dot product

    if (lane == 0) {
        // stable softplus
        float dot = prod;
        float base = fmaxf(dot, 0.0f) + log1pf(expf(-fabsf(dot)));

        float incr = 0.0f;
        if (has_prev) {
            float t_last = __ldg(&row[idx]);
            float x_raw  = __ldg(&x_pad[(size_t)e * L + idx]);
            float z = (x_raw - 0.5f) * 4.0f;              // (x-MEAN)/VAR, VAR=0.25
            float sig = 1.0f / (1.0f + expf(-z));
            float alpha = __ldg(alpha_p);
            float beta  = __ldg(beta_p);
            incr = alpha * sig * expf(-beta * (tq - t_last));
        }
        out[e] = base + incr;
    }
}

extern "C" void kernel_launch(void* const* d_in, const int* in_sizes, int n_in,
                              void* d_out, int out_size)
{
    const int*   src     = (const int*)  d_in[0];
    const int*   dst     = (const int*)  d_in[1];
    const float* t       = (const float*)d_in[2];
    const float* x_pad   = (const float*)d_in[3];
    const float* t_pad   = (const float*)d_in[4];
    const float* emb_src = (const float*)d_in[5];
    const float* emb_dst = (const float*)d_in[6];
    const float* alpha   = (const float*)d_in[7];
    const float* beta    = (const float*)d_in[8];
    float* out = (float*)d_out;

    const int E = in_sizes[2];               // query events
    const int L = in_sizes[4] / E;           // padded history length (2048)

    const int threads = 256;                 // 8 warps -> 8 events per block
    const int blocks = (E * 32 + threads - 1) / threads;
    markov_kernel<<<blocks, threads>>>(src, dst, t, x_pad, t_pad,
                                       emb_src, emb_dst, alpha, beta,
                                       out, E, L);
}

// round 2
// speedup vs baseline: 1.5952x; 1.5952x over previous
#include <cuda_runtime.h>
#include <math.h>

#define NCOMP 20

// 4 events per warp, 8 lanes per event. 3-round 8-ary search over sorted row.
__global__ void __launch_bounds__(256) markov_kernel(
        const int* __restrict__ src,
        const int* __restrict__ dst,
        const float* __restrict__ t,
        const float* __restrict__ x_pad,
        const float* __restrict__ t_pad,
        const float* __restrict__ emb_src,
        const float* __restrict__ emb_dst,
        const float* __restrict__ alpha_p,
        const float* __restrict__ beta_p,
        float* __restrict__ out,
        int E, int L)
{
    const int lane = threadIdx.x & 31;
    const int sub  = lane >> 3;       // event slot within warp (0..3)
    const int sl   = lane & 7;        // sublane within event (0..7)
    const int warp = (blockIdx.x * blockDim.x + threadIdx.x) >> 5;
    const int e = warp * 4 + sub;
    if (e >= E) return;

    const float tq = __ldg(&t[e]);
    const float* __restrict__ row = t_pad + (size_t)e * L;

    // ---- start embedding loads early (independent of the search) ----
    const int s = __ldg(&src[e]);
    const int d = __ldg(&dst[e]);
    const float* es = emb_src + (size_t)s * NCOMP;
    const float* ed = emb_dst + (size_t)d * NCOMP;
    float a0 = __ldg(&es[sl]),     b0 = __ldg(&ed[sl]);
    float a1 = __ldg(&es[sl + 8]), b1 = __ldg(&ed[sl + 8]);
    float a2 = 0.0f, b2 = 0.0f;
    if (sl < 4) { a2 = __ldg(&es[sl + 16]); b2 = __ldg(&ed[sl + 16]); }

    const int shift = sub * 8;

    // ---- round 1: 8 chunks of 256 floats; probe each chunk's last element ----
    float v1 = __ldg(&row[(sl + 1) * 256 - 1]);
    unsigned bb = __ballot_sync(0xffffffffu, v1 < tq);
    int c1 = __popc((bb >> shift) & 0xffu);
    int c1i = min(c1, 7);

    // ---- round 2: 8 sub-chunks of 32 floats within chunk c1i ----
    const int base1 = c1i * 256;
    float v2 = __ldg(&row[base1 + (sl + 1) * 32 - 1]);
    bb = __ballot_sync(0xffffffffu, v2 < tq);
    int c2 = __popc((bb >> shift) & 0xffu);
    int c2i = min(c2, 7);

    // ---- round 3: 32-float sub-chunk, float4 per lane (coalesced 128 B) ----
    const int base2 = base1 + c2i * 32;
    float4 q = *reinterpret_cast<const float4*>(row + base2 + sl * 4);
    int loc = (q.x < tq) + (q.y < tq) + (q.z < tq) + (q.w < tq);
    #pragma unroll
    for (int off = 1; off < 8; off <<= 1)
        loc += __shfl_xor_sync(0xffffffffu, loc, off);  // sum within 8-lane segment

    const int cnt = c1i * 256 + c2i * 32 + loc;   // clamped path yields 2048 correctly
    const bool has_prev = (cnt > 0);
    const int idx = has_prev ? (cnt - 1) : 0;

    // ---- dot-product reduction within 8-lane segment ----
    float prod = a0 * b0 + a1 * b1 + a2 * b2;
    #pragma unroll
    for (int off = 1; off < 8; off <<= 1)
        prod += __shfl_xor_sync(0xffffffffu, prod, off);

    if (sl == 0) {
        float dot = prod;
        float base = fmaxf(dot, 0.0f) + log1pf(expf(-fabsf(dot)));  // softplus

        float incr = 0.0f;
        if (has_prev) {
            float t_last = __ldg(&row[idx]);   // L1 hit: sector touched by r2/r3 probes
            float x_raw  = __ldg(&x_pad[(size_t)e * L + idx]);
            float z = (x_raw - 0.5f) * 4.0f;   // (x - MEAN) / VAR, VAR = 0.25
            float sig = 1.0f / (1.0f + expf(-z));
            float alpha = __ldg(alpha_p);
            float beta  = __ldg(beta_p);
            incr = alpha * sig * expf(-beta * (tq - t_last));
        }
        out[e] = base + incr;
    }
}

extern "C" void kernel_launch(void* const* d_in, const int* in_sizes, int n_in,
                              void* d_out, int out_size)
{
    const int*   src     = (const int*)  d_in[0];
    const int*   dst     = (const int*)  d_in[1];
    const float* t       = (const float*)d_in[2];
    const float* x_pad   = (const float*)d_in[3];
    const float* t_pad   = (const float*)d_in[4];
    const float* emb_src = (const float*)d_in[5];
    const float* emb_dst = (const float*)d_in[6];
    const float* alpha   = (const float*)d_in[7];
    const float* beta    = (const float*)d_in[8];
    float* out = (float*)d_out;

    const int E = in_sizes[2];
    const int L = in_sizes[4] / E;     // 2048

    // 4 events per warp -> E/4 warps; 256 threads = 8 warps = 32 events/block
    const int threads = 256;
    const int events_per_block = 32;
    const int blocks = (E + events_per_block - 1) / events_per_block;
    markov_kernel<<<blocks, threads>>>(src, dst, t, x_pad, t_pad,
                                       emb_src, emb_dst, alpha, beta,
                                       out, E, L);
}